// round 2
// baseline (speedup 1.0000x reference)
#include <cuda_runtime.h>

#define NN 200000
#define CC 256
#define MM 50000
#define VCD 48   // 16 vector channels * 3 spatial dims

// Scratch accumulators (device globals; no allocation allowed in kernel_launch)
__device__ float g_s_sum[(size_t)MM * CC];   // 51.2 MB
__device__ float g_v_sum[(size_t)MM * VCD];  // 9.6 MB
__device__ float g_cnt[MM];
__device__ int   g_seg_is64;

// ---------------------------------------------------------------------------
// Probe the segment-index buffer's dtype. motif ids are < 50000 < 2^31, so if
// the buffer is int64 every odd 32-bit word of the first 1024 entries is 0.
// For int32 data those words are random ids (P(all 1024 == 0) ~ 0).
// ---------------------------------------------------------------------------
__global__ void probe_seg_kernel(const int* __restrict__ seg32) {
    __shared__ int any_nonzero;
    if (threadIdx.x == 0) any_nonzero = 0;
    __syncthreads();
    for (int i = threadIdx.x; i < 1024; i += blockDim.x) {
        if (seg32[2 * i + 1] != 0) any_nonzero = 1;
    }
    __syncthreads();
    if (threadIdx.x == 0) g_seg_is64 = (any_nonzero == 0) ? 1 : 0;
}

__device__ __forceinline__ int load_seg(const void* seg, int n, int is64) {
    if (is64) return (int)((const long long*)seg)[n];
    return ((const int*)seg)[n];
}

// ---------------------------------------------------------------------------
// Zero accumulators (grid-stride, float4)
// ---------------------------------------------------------------------------
__global__ void zero_kernel() {
    size_t i = blockIdx.x * (size_t)blockDim.x + threadIdx.x;
    size_t stride = (size_t)gridDim.x * blockDim.x;
    float4 z = make_float4(0.f, 0.f, 0.f, 0.f);
    float4* ps = (float4*)g_s_sum;
    size_t ns = (size_t)MM * CC / 4;
    for (size_t j = i; j < ns; j += stride) ps[j] = z;
    float4* pv = (float4*)g_v_sum;
    size_t nv = (size_t)MM * VCD / 4;
    for (size_t j = i; j < nv; j += stride) pv[j] = z;
    for (size_t j = i; j < MM; j += stride) g_cnt[j] = 0.f;
}

// Vectorized global reduction: 1 L2 atomic op per 16 bytes instead of 4.
__device__ __forceinline__ void red_add_v4(float* addr, float4 val) {
    asm volatile("red.global.add.v4.f32 [%0], {%1,%2,%3,%4};"
                 :: "l"(addr), "f"(val.x), "f"(val.y), "f"(val.z), "f"(val.w)
                 : "memory");
}

// ---------------------------------------------------------------------------
// Scatter-add s: one thread per (node, 4-channel chunk).
// ---------------------------------------------------------------------------
__global__ void scatter_s_kernel(const float* __restrict__ s,
                                 const void* __restrict__ seg) {
    long long i = blockIdx.x * (long long)blockDim.x + threadIdx.x;
    if (i >= (long long)NN * (CC / 4)) return;
    int n  = (int)(i >> 6);   // CC/4 == 64
    int c4 = (int)(i & 63);
    int m = load_seg(seg, n, g_seg_is64);
    if ((unsigned)m >= MM) return;   // safety: never write OOB
    float4 val = ((const float4*)s)[i];
    red_add_v4(&g_s_sum[(size_t)m * CC + c4 * 4], val);
}

// ---------------------------------------------------------------------------
// Scatter-add v (+ counts): one thread per (node, 4-float chunk of the 48).
// ---------------------------------------------------------------------------
__global__ void scatter_v_kernel(const float* __restrict__ v,
                                 const void* __restrict__ seg) {
    long long i = blockIdx.x * (long long)blockDim.x + threadIdx.x;
    if (i >= (long long)NN * (VCD / 4)) return;
    int n  = (int)(i / 12);
    int j4 = (int)(i % 12);
    int m = load_seg(seg, n, g_seg_is64);
    if ((unsigned)m >= MM) return;
    float4 val = ((const float4*)v)[i];
    red_add_v4(&g_v_sum[(size_t)m * VCD + j4 * 4], val);
    if (j4 == 0) atomicAdd(&g_cnt[m], 1.0f);
}

// ---------------------------------------------------------------------------
// s_out = (s_sum / max(cnt,1)) @ Ws^T + bs
// Tiled fp32 SGEMM: 64x64 block tile, BK=16, 256 threads, 4x4 microtile.
// Mean-division fused into the A-tile load (per-row scale).
// ---------------------------------------------------------------------------
__global__ void __launch_bounds__(256)
gemm_s_kernel(const float* __restrict__ Ws, const float* __restrict__ bs,
              float* __restrict__ out) {
    __shared__ float As[16][64];
    __shared__ float Bs[16][64];
    __shared__ float invc[64];

    int tid = threadIdx.x;
    int tx = tid & 15, ty = tid >> 4;
    int mb = blockIdx.y, nb = blockIdx.x;
    int m0 = mb * 64, n0 = nb * 64;

    if (tid < 64) {
        int gm = m0 + tid;
        float c = (gm < MM) ? g_cnt[gm] : 1.0f;
        invc[tid] = 1.0f / fmaxf(c, 1.0f);
    }
    __syncthreads();

    int lr = tid >> 2;   // 0..63: tile row being loaded
    int lq = tid & 3;    // 0..3:  which float4 along K
    int gm = m0 + lr;
    bool mvalid = (gm < MM);
    const float* Arow = g_s_sum + (size_t)gm * CC;
    const float* Brow = Ws + (size_t)(n0 + lr) * CC;
    float sc = invc[lr];

    float acc[4][4];
#pragma unroll
    for (int i = 0; i < 4; i++)
#pragma unroll
        for (int j = 0; j < 4; j++) acc[i][j] = 0.f;

    for (int kt = 0; kt < CC; kt += 16) {
        float4 a = mvalid ? *(const float4*)(Arow + kt + lq * 4)
                          : make_float4(0.f, 0.f, 0.f, 0.f);
        a.x *= sc; a.y *= sc; a.z *= sc; a.w *= sc;
        float4 b = *(const float4*)(Brow + kt + lq * 4);
        As[lq * 4 + 0][lr] = a.x; As[lq * 4 + 1][lr] = a.y;
        As[lq * 4 + 2][lr] = a.z; As[lq * 4 + 3][lr] = a.w;
        Bs[lq * 4 + 0][lr] = b.x; Bs[lq * 4 + 1][lr] = b.y;
        Bs[lq * 4 + 2][lr] = b.z; Bs[lq * 4 + 3][lr] = b.w;
        __syncthreads();
#pragma unroll
        for (int kk = 0; kk < 16; kk++) {
            float4 av = *(const float4*)&As[kk][ty * 4];
            float4 bv = *(const float4*)&Bs[kk][tx * 4];
            float aa[4] = {av.x, av.y, av.z, av.w};
            float bb[4] = {bv.x, bv.y, bv.z, bv.w};
#pragma unroll
            for (int i = 0; i < 4; i++)
#pragma unroll
                for (int j = 0; j < 4; j++) acc[i][j] += aa[i] * bb[j];
        }
        __syncthreads();
    }

    float4 bsv = ((const float4*)bs)[nb * 16 + tx];
#pragma unroll
    for (int i = 0; i < 4; i++) {
        int m = m0 + ty * 4 + i;
        if (m < MM) {
            float4 o;
            o.x = acc[i][0] + bsv.x;
            o.y = acc[i][1] + bsv.y;
            o.z = acc[i][2] + bsv.z;
            o.w = acc[i][3] + bsv.w;
            *(float4*)(out + (size_t)m * CC + n0 + tx * 4) = o;
        }
    }
}

// ---------------------------------------------------------------------------
// v_out[m][o][d] = (1/max(cnt,1)) * sum_c Wv[o][c] * v_sum[m][c][d] + bv[o]
// ---------------------------------------------------------------------------
__global__ void v_out_kernel(const float* __restrict__ Wv,
                             const float* __restrict__ bv,
                             float* __restrict__ out_v) {
    int i = blockIdx.x * blockDim.x + threadIdx.x;
    if (i >= MM * VCD) return;
    int m = i / 48;
    int r = i % 48;
    int o = r / 3, d = r % 3;
    float inv = 1.0f / fmaxf(g_cnt[m], 1.0f);
    const float* vm = g_v_sum + (size_t)m * 48;
    const float* w  = Wv + o * 16;
    float sum = 0.f;
#pragma unroll
    for (int c = 0; c < 16; c++) sum += w[c] * vm[c * 3 + d];
    out_v[i] = sum * inv + bv[o];
}

// ---------------------------------------------------------------------------
extern "C" void kernel_launch(void* const* d_in, const int* in_sizes, int n_in,
                              void* d_out, int out_size) {
    const float* s   = (const float*)d_in[0];
    const float* v   = (const float*)d_in[1];
    const void*  seg = d_in[2];
    const float* Ws  = (const float*)d_in[3];
    const float* bs  = (const float*)d_in[4];
    const float* Wv  = (const float*)d_in[5];
    const float* bv  = (const float*)d_in[6];
    float* out_s = (float*)d_out;
    float* out_v = out_s + (size_t)MM * CC;

    probe_seg_kernel<<<1, 256>>>((const int*)seg);
    zero_kernel<<<2048, 256>>>();

    long long s_threads = (long long)NN * (CC / 4);
    scatter_s_kernel<<<(int)((s_threads + 255) / 256), 256>>>(s, seg);

    long long v_threads = (long long)NN * (VCD / 4);
    scatter_v_kernel<<<(int)((v_threads + 255) / 256), 256>>>(v, seg);

    dim3 gg(CC / 64, (MM + 63) / 64);
    gemm_s_kernel<<<gg, 256>>>(Ws, bs, out_s);

    v_out_kernel<<<(MM * VCD + 255) / 256, 256>>>(Wv, bv, out_v);
}

// round 4
// speedup vs baseline: 2.3550x; 2.3550x over previous
#include <cuda_runtime.h>
#include <cstdint>

#define NN 200000
#define CC 256
#define MM 50000
#define VCD 48   // 16 vector channels * 3 spatial dims

// Scratch accumulators (device globals; no allocation allowed in kernel_launch)
__device__ float g_s_sum[(size_t)MM * CC];   // 51.2 MB
__device__ float g_v_sum[(size_t)MM * VCD];  // 9.6 MB
__device__ float g_cnt[MM];
__device__ int   g_seg_is64;

// ============================ helpers ======================================
__device__ __forceinline__ uint32_t smem_u32(const void* p) {
    uint32_t a;
    asm("{ .reg .u64 t; cvta.to.shared.u64 t, %1; cvt.u32.u64 %0, t; }"
        : "=r"(a) : "l"(p));
    return a;
}
__device__ __forceinline__ float to_tf32(float x) {
    float r;
    asm("cvt.rna.tf32.f32 %0, %1;" : "=f"(r) : "f"(x));
    return r;
}
__device__ __forceinline__ void ldsm_x4(uint32_t* r, uint32_t addr) {
    asm volatile("ldmatrix.sync.aligned.m8n8.x4.shared.b16 {%0,%1,%2,%3}, [%4];"
        : "=r"(r[0]), "=r"(r[1]), "=r"(r[2]), "=r"(r[3]) : "r"(addr));
}
__device__ __forceinline__ void ldsm_x2(uint32_t* r, uint32_t addr) {
    asm volatile("ldmatrix.sync.aligned.m8n8.x2.shared.b16 {%0,%1}, [%2];"
        : "=r"(r[0]), "=r"(r[1]) : "r"(addr));
}
__device__ __forceinline__ void mma_tf32(float* c, const uint32_t* a, const uint32_t* b) {
    asm volatile(
        "mma.sync.aligned.m16n8k8.row.col.f32.tf32.tf32.f32 "
        "{%0,%1,%2,%3}, {%4,%5,%6,%7}, {%8,%9}, {%0,%1,%2,%3};"
        : "+f"(c[0]), "+f"(c[1]), "+f"(c[2]), "+f"(c[3])
        : "r"(a[0]), "r"(a[1]), "r"(a[2]), "r"(a[3]), "r"(b[0]), "r"(b[1]));
}
__device__ __forceinline__ void red_add_v4(float* addr, float4 val) {
    asm volatile("red.global.add.v4.f32 [%0], {%1,%2,%3,%4};"
                 :: "l"(addr), "f"(val.x), "f"(val.y), "f"(val.z), "f"(val.w)
                 : "memory");
}

// ---------------------------------------------------------------------------
// Probe the segment-index buffer's dtype (int64 vs int32).
// ---------------------------------------------------------------------------
__global__ void probe_seg_kernel(const int* __restrict__ seg32) {
    __shared__ int any_nonzero;
    if (threadIdx.x == 0) any_nonzero = 0;
    __syncthreads();
    for (int i = threadIdx.x; i < 1024; i += blockDim.x)
        if (seg32[2 * i + 1] != 0) any_nonzero = 1;
    __syncthreads();
    if (threadIdx.x == 0) g_seg_is64 = (any_nonzero == 0) ? 1 : 0;
}
__device__ __forceinline__ int load_seg(const void* seg, int n, int is64) {
    if (is64) return (int)((const long long*)seg)[n];
    return ((const int*)seg)[n];
}

// ---------------------------------------------------------------------------
__global__ void zero_kernel() {
    size_t i = blockIdx.x * (size_t)blockDim.x + threadIdx.x;
    size_t stride = (size_t)gridDim.x * blockDim.x;
    float4 z = make_float4(0.f, 0.f, 0.f, 0.f);
    float4* ps = (float4*)g_s_sum;
    size_t ns = (size_t)MM * CC / 4;
    for (size_t j = i; j < ns; j += stride) ps[j] = z;
    float4* pv = (float4*)g_v_sum;
    size_t nv = (size_t)MM * VCD / 4;
    for (size_t j = i; j < nv; j += stride) pv[j] = z;
    for (size_t j = i; j < MM; j += stride) g_cnt[j] = 0.f;
}

__global__ void scatter_s_kernel(const float* __restrict__ s,
                                 const void* __restrict__ seg) {
    long long i = blockIdx.x * (long long)blockDim.x + threadIdx.x;
    if (i >= (long long)NN * (CC / 4)) return;
    int n  = (int)(i >> 6);
    int c4 = (int)(i & 63);
    int m = load_seg(seg, n, g_seg_is64);
    if ((unsigned)m >= MM) return;
    float4 val = ((const float4*)s)[i];
    red_add_v4(&g_s_sum[(size_t)m * CC + c4 * 4], val);
}

__global__ void scatter_v_kernel(const float* __restrict__ v,
                                 const void* __restrict__ seg) {
    long long i = blockIdx.x * (long long)blockDim.x + threadIdx.x;
    if (i >= (long long)NN * (VCD / 4)) return;
    int n  = (int)(i / 12);
    int j4 = (int)(i % 12);
    int m = load_seg(seg, n, g_seg_is64);
    if ((unsigned)m >= MM) return;
    float4 val = ((const float4*)v)[i];
    red_add_v4(&g_v_sum[(size_t)m * VCD + j4 * 4], val);
    if (j4 == 0) atomicAdd(&g_cnt[m], 1.0f);
}

// ---------------------------------------------------------------------------
// tf32 mma.sync GEMM with 2xTF32 A-split, mean fused into A load.
// BM=128, BN=128, BK=32. 8 warps: 2(M)x4(N); each warp 64x32 via 4x4 m16n8k8
// fragments. SMEM tiles stored as [row][32 floats], 16B chunks XOR-swizzled by
// (chunk ^ row&7) -> conflict-free ldmatrix.
// ---------------------------------------------------------------------------
#define SMO_INVC 0
#define SMO_BS   512
#define SMO_AHI  1024
#define SMO_ALO  (1024 + 16384)
#define SMO_B    (1024 + 32768)
#define SMO_TOTAL (1024 + 49152)

__global__ void __launch_bounds__(256, 2)
gemm_s_mma(const float* __restrict__ Ws, const float* __restrict__ bs,
           float* __restrict__ out) {
    extern __shared__ char sm[];
    uint32_t sb = smem_u32(sm);
    int tid = threadIdx.x, wid = tid >> 5, lane = tid & 31;
    int wm = wid & 1, wn = wid >> 1;
    int m0 = blockIdx.y * 128, n0 = blockIdx.x * 128;

    float* invc = (float*)(sm + SMO_INVC);
    float* bssh = (float*)(sm + SMO_BS);
    if (tid < 128) {
        int gm = m0 + tid;
        float c = (gm < MM) ? g_cnt[gm] : 1.0f;
        invc[tid] = 1.0f / fmaxf(c, 1.0f);
        bssh[tid] = bs[n0 + tid];
    }
    __syncthreads();

    float acc[4][4][4];
#pragma unroll
    for (int a = 0; a < 4; a++)
#pragma unroll
        for (int b = 0; b < 4; b++)
#pragma unroll
            for (int c = 0; c < 4; c++) acc[a][b][c] = 0.f;

    // per-lane ldmatrix row precompute
    int r8 = lane & 7;
    int halfA = (lane >> 3) & 1;
    int ksubA = lane >> 4;          // 0,0,1,1 per 8-lane group
    int ksubB = (lane >> 3) & 1;
    uint32_t aRowOff[4]; int aRsw[4];
#pragma unroll
    for (int mi = 0; mi < 4; mi++) {
        int row = wm * 64 + mi * 16 + halfA * 8 + r8;
        aRowOff[mi] = row * 128;
        aRsw[mi] = row & 7;
    }
    uint32_t bRowOff[4];
#pragma unroll
    for (int ni = 0; ni < 4; ni++)
        bRowOff[ni] = (wn * 32 + ni * 8 + r8) * 128;

    for (int ch = 0; ch < 8; ch++) {
        int kt = ch * 32;
        // ---- A chunk: 128x32, scale by invc, split hi/lo
#pragma unroll
        for (int i = 0; i < 4; i++) {
            int f = tid + 256 * i;
            int row = f >> 3, q = f & 7;
            int gm = m0 + row;
            float4 a = (gm < MM)
                ? *(const float4*)(g_s_sum + (size_t)gm * CC + kt + q * 4)
                : make_float4(0.f, 0.f, 0.f, 0.f);
            float sc = invc[row];
            a.x *= sc; a.y *= sc; a.z *= sc; a.w *= sc;
            float4 hi, lo;
            hi.x = to_tf32(a.x); lo.x = a.x - hi.x;
            hi.y = to_tf32(a.y); lo.y = a.y - hi.y;
            hi.z = to_tf32(a.z); lo.z = a.z - hi.z;
            hi.w = to_tf32(a.w); lo.w = a.w - hi.w;
            uint32_t off = row * 128 + ((q ^ (row & 7)) << 4);
            *(float4*)(sm + SMO_AHI + off) = hi;
            *(float4*)(sm + SMO_ALO + off) = lo;
        }
        // ---- B chunk: 128 out-channels x 32 k (rounded to tf32)
#pragma unroll
        for (int i = 0; i < 4; i++) {
            int f = tid + 256 * i;
            int row = f >> 3, q = f & 7;
            float4 b = *(const float4*)(Ws + (size_t)(n0 + row) * CC + kt + q * 4);
            b.x = to_tf32(b.x); b.y = to_tf32(b.y);
            b.z = to_tf32(b.z); b.w = to_tf32(b.w);
            uint32_t off = row * 128 + ((q ^ (row & 7)) << 4);
            *(float4*)(sm + SMO_B + off) = b;
        }
        __syncthreads();

#pragma unroll
        for (int ks = 0; ks < 4; ks++) {
            int ks2 = ks * 2;
            uint32_t bf[4][2];
#pragma unroll
            for (int ni = 0; ni < 4; ni++)
                ldsm_x2(bf[ni], sb + SMO_B + bRowOff[ni] + (((ks2 + ksubB) ^ r8) << 4));
#pragma unroll
            for (int mi = 0; mi < 4; mi++) {
                uint32_t ah[4], al[4];
                uint32_t ca = ((uint32_t)((ks2 + ksubA) ^ aRsw[mi])) << 4;
                ldsm_x4(ah, sb + SMO_AHI + aRowOff[mi] + ca);
                ldsm_x4(al, sb + SMO_ALO + aRowOff[mi] + ca);
#pragma unroll
                for (int ni = 0; ni < 4; ni++) {
                    mma_tf32(acc[mi][ni], ah, bf[ni]);
                    mma_tf32(acc[mi][ni], al, bf[ni]);
                }
            }
        }
        __syncthreads();
    }

    // ---- epilogue
    int lr = lane >> 2, lc2 = 2 * (lane & 3);
#pragma unroll
    for (int mi = 0; mi < 4; mi++) {
#pragma unroll
        for (int ni = 0; ni < 4; ni++) {
            int lcol = wn * 32 + ni * 8 + lc2;
            float b0 = bssh[lcol], b1 = bssh[lcol + 1];
            int row0 = m0 + wm * 64 + mi * 16 + lr;
            if (row0 < MM) {
                float2 o = make_float2(acc[mi][ni][0] + b0, acc[mi][ni][1] + b1);
                *(float2*)(out + (size_t)row0 * CC + n0 + lcol) = o;
            }
            int row1 = row0 + 8;
            if (row1 < MM) {
                float2 o = make_float2(acc[mi][ni][2] + b0, acc[mi][ni][3] + b1);
                *(float2*)(out + (size_t)row1 * CC + n0 + lcol) = o;
            }
        }
    }
}

// ---------------------------------------------------------------------------
__global__ void v_out_kernel(const float* __restrict__ Wv,
                             const float* __restrict__ bv,
                             float* __restrict__ out_v) {
    int i = blockIdx.x * blockDim.x + threadIdx.x;
    if (i >= MM * VCD) return;
    int m = i / 48;
    int r = i % 48;
    int o = r / 3, d = r % 3;
    float inv = 1.0f / fmaxf(g_cnt[m], 1.0f);
    const float* vm = g_v_sum + (size_t)m * 48;
    const float* w  = Wv + o * 16;
    float sum = 0.f;
#pragma unroll
    for (int c = 0; c < 16; c++) sum += w[c] * vm[c * 3 + d];
    out_v[i] = sum * inv + bv[o];
}

// ---------------------------------------------------------------------------
extern "C" void kernel_launch(void* const* d_in, const int* in_sizes, int n_in,
                              void* d_out, int out_size) {
    const float* s   = (const float*)d_in[0];
    const float* v   = (const float*)d_in[1];
    const void*  seg = d_in[2];
    const float* Ws  = (const float*)d_in[3];
    const float* bs  = (const float*)d_in[4];
    const float* Wv  = (const float*)d_in[5];
    const float* bv  = (const float*)d_in[6];
    float* out_s = (float*)d_out;
    float* out_v = out_s + (size_t)MM * CC;

    static int smem_set = 0;
    if (!smem_set) {
        cudaFuncSetAttribute(gemm_s_mma,
                             cudaFuncAttributeMaxDynamicSharedMemorySize, SMO_TOTAL);
        smem_set = 1;
    }

    probe_seg_kernel<<<1, 256>>>((const int*)seg);
    zero_kernel<<<2048, 256>>>();

    long long s_threads = (long long)NN * (CC / 4);
    scatter_s_kernel<<<(int)((s_threads + 255) / 256), 256>>>(s, seg);

    long long v_threads = (long long)NN * (VCD / 4);
    scatter_v_kernel<<<(int)((v_threads + 255) / 256), 256>>>(v, seg);

    dim3 gg(CC / 128, (MM + 127) / 128);
    gemm_s_mma<<<gg, 256, SMO_TOTAL>>>(Ws, bs, out_s);

    v_out_kernel<<<(MM * VCD + 255) / 256, 256>>>(Wv, bv, out_v);
}